// round 14
// baseline (speedup 1.0000x reference)
#include <cuda_runtime.h>

// Problem constants (fixed-shape problem)
#define NB 1024
#define ND 64
#define NL 8
#define NK 16
#define DS 68                 // smem row stride in floats (16B-aligned, de-conflicted)
#define MAT (ND * ND)         // 4096
#define PLANE (NB * ND * ND)  // 4,194,304

// Ping-pong scratch for intermediate rho (re plane then im plane). 32 MB static.
__device__ float g_qhmm_scratch[2 * NB * ND * ND];

typedef unsigned long long ull;

union Q4 { float4 v; ull u[2]; float f[4]; };
union P2 { ull u; float2 f; };

__device__ __forceinline__ ull dup2(float x) {
    ull r; asm("mov.b64 %0, {%1, %2};" : "=l"(r) : "f"(x), "f"(x)); return r;
}
__device__ __forceinline__ void fma2(ull& d, ull a, ull b) {
    asm("fma.rn.f32x2 %0, %1, %2, %0;" : "+l"(d) : "l"(a), "l"(b));
}
__device__ __forceinline__ ull neg2(ull a, ull negone) {
    ull r; asm("mul.rn.f32x2 %0, %1, %2;" : "=l"(r) : "l"(a), "l"(negone)); return r;
}

// One layer: for each batch b (one block), rho_out = sum_k K_k rho_in K_k^H
// Thread map: 16x16 threads, each owns a 4x4 complex tile of the 64x64 output.
//   Phase A: T = K_k @ rho     (T stored transposed in smem: Tt[l][i])
//   Phase B: C += T @ K_k^H    (accumulated in registers across k)
// K is staged transposed in smem (Kt[j][i]) so BOTH phases read it either as a
// 16B broadcast (row side) or as contiguous float4 (column side) — conflict-free.
__global__ void __launch_bounds__(256, 2)
qhmm_layer_kernel(const float* __restrict__ rin_re, const float* __restrict__ rin_im,
                  const float* __restrict__ kl_re,  const float* __restrict__ kl_im,
                  float* __restrict__ rout_re, float* __restrict__ rout_im)
{
    extern __shared__ float s[];
    float* s_rr = s;                 // rho real   [j][l], stride DS
    float* s_ri = s_rr + ND * DS;    // rho imag
    float* s_kr = s_ri + ND * DS;    // Kt real    [j][i]  (K transposed)
    float* s_ki = s_kr + ND * DS;    // Kt imag
    float* s_tr = s_ki + ND * DS;    // Tt real    [l][i]  (T transposed)
    float* s_ti = s_tr + ND * DS;    // Tt imag

    const int b   = blockIdx.x;
    const int tid = threadIdx.x;
    const int tx  = tid & 15;
    const int ty  = tid >> 4;
    const int i0  = ty * 4;   // output row base
    const int c0  = tx * 4;   // output col base (l in phase A, m in phase B)

    // Load rho for this batch into smem (coalesced reads, stride-DS rows).
    {
        const float* gr = rin_re + b * MAT;
        const float* gi = rin_im + b * MAT;
        #pragma unroll
        for (int e = tid; e < MAT; e += 256) {
            int i = e >> 6, j = e & 63;
            s_rr[i * DS + j] = gr[e];
            s_ri[i * DS + j] = gi[e];
        }
    }

    // Output accumulators: C[i0+ii][c0 + 2p + {0,1}], packed f32x2 along columns.
    ull cr[4][2], ci[4][2];
    #pragma unroll
    for (int a = 0; a < 4; a++) {
        #pragma unroll
        for (int p = 0; p < 2; p++) { cr[a][p] = 0ull; ci[a][p] = 0ull; }
    }

    const ull NEG1 = dup2(-1.0f);

    for (int k = 0; k < NK; k++) {
        __syncthreads();  // previous phase B done reading s_k*/s_t*
        // Stage K_k transposed: Kt[j][i] = K[i][j]
        {
            const float* gkr = kl_re + k * MAT;
            const float* gki = kl_im + k * MAT;
            #pragma unroll
            for (int e = tid; e < MAT; e += 256) {
                int i = e >> 6, j = e & 63;
                s_kr[j * DS + i] = gkr[e];
                s_ki[j * DS + i] = gki[e];
            }
        }
        __syncthreads();

        // ---- Phase A: T[i][l] = sum_j K[i][j] * rho[j][l] ----
        ull tr[4][2], ti[4][2];
        #pragma unroll
        for (int a = 0; a < 4; a++) {
            #pragma unroll
            for (int p = 0; p < 2; p++) { tr[a][p] = 0ull; ti[a][p] = 0ull; }
        }
        #pragma unroll 4
        for (int j = 0; j < ND; j++) {
            Q4 ar4, ai4, br4, bi4;
            ar4.v = *(const float4*)(s_kr + j * DS + i0);  // K[i0..i0+3][j] (broadcast)
            ai4.v = *(const float4*)(s_ki + j * DS + i0);
            br4.v = *(const float4*)(s_rr + j * DS + c0);  // rho[j][c0..c0+3] (vector)
            bi4.v = *(const float4*)(s_ri + j * DS + c0);
            #pragma unroll
            for (int ii = 0; ii < 4; ii++) {
                ull a_r  = dup2(ar4.f[ii]);
                ull a_i  = dup2(ai4.f[ii]);
                ull na_i = neg2(a_i, NEG1);
                // tr += ar*br - ai*bi ; ti += ar*bi + ai*br
                fma2(tr[ii][0], a_r,  br4.u[0]);
                fma2(tr[ii][0], na_i, bi4.u[0]);
                fma2(tr[ii][1], a_r,  br4.u[1]);
                fma2(tr[ii][1], na_i, bi4.u[1]);
                fma2(ti[ii][0], a_r,  bi4.u[0]);
                fma2(ti[ii][0], a_i,  br4.u[0]);
                fma2(ti[ii][1], a_r,  bi4.u[1]);
                fma2(ti[ii][1], a_i,  br4.u[1]);
            }
        }
        // Write T transposed: Tt[l][i]
        #pragma unroll
        for (int ii = 0; ii < 4; ii++) {
            #pragma unroll
            for (int p = 0; p < 2; p++) {
                P2 r, m; r.u = tr[ii][p]; m.u = ti[ii][p];
                int l = c0 + 2 * p;
                s_tr[(l    ) * DS + i0 + ii] = r.f.x;
                s_tr[(l + 1) * DS + i0 + ii] = r.f.y;
                s_ti[(l    ) * DS + i0 + ii] = m.f.x;
                s_ti[(l + 1) * DS + i0 + ii] = m.f.y;
            }
        }
        __syncthreads();

        // ---- Phase B: C[i][m] += sum_l T[i][l] * conj(K[m][l]) ----
        #pragma unroll 4
        for (int l = 0; l < ND; l++) {
            Q4 ar4, ai4, br4, bi4;
            ar4.v = *(const float4*)(s_tr + l * DS + i0);  // T[i0..i0+3][l] (broadcast)
            ai4.v = *(const float4*)(s_ti + l * DS + i0);
            br4.v = *(const float4*)(s_kr + l * DS + c0);  // K[c0..c0+3][l] (vector)
            bi4.v = *(const float4*)(s_ki + l * DS + c0);
            #pragma unroll
            for (int ii = 0; ii < 4; ii++) {
                ull t_r  = dup2(ar4.f[ii]);
                ull t_i  = dup2(ai4.f[ii]);
                ull nt_r = neg2(t_r, NEG1);
                // cr += Tr*Kr + Ti*Ki ; ci += Ti*Kr - Tr*Ki   (conj on K)
                fma2(cr[ii][0], t_r,  br4.u[0]);
                fma2(cr[ii][0], t_i,  bi4.u[0]);
                fma2(cr[ii][1], t_r,  br4.u[1]);
                fma2(cr[ii][1], t_i,  bi4.u[1]);
                fma2(ci[ii][0], t_i,  br4.u[0]);
                fma2(ci[ii][0], nt_r, bi4.u[0]);
                fma2(ci[ii][1], t_i,  br4.u[1]);
                fma2(ci[ii][1], nt_r, bi4.u[1]);
            }
        }
    }

    // Write result
    float* orr = rout_re + b * MAT;
    float* ori = rout_im + b * MAT;
    #pragma unroll
    for (int ii = 0; ii < 4; ii++) {
        #pragma unroll
        for (int p = 0; p < 2; p++) {
            P2 r, m; r.u = cr[ii][p]; m.u = ci[ii][p];
            int off = (i0 + ii) * ND + c0 + 2 * p;
            *(float2*)(orr + off) = r.f;
            *(float2*)(ori + off) = m.f;
        }
    }
}

extern "C" void kernel_launch(void* const* d_in, const int* in_sizes, int n_in,
                              void* d_out, int out_size)
{
    const float* st_re = (const float*)d_in[0];  // [B,D,D]
    const float* st_im = (const float*)d_in[1];  // [B,D,D]
    const float* kr_re = (const float*)d_in[2];  // [L,K,D,D]
    const float* kr_im = (const float*)d_in[3];  // [L,K,D,D]

    float* out    = (float*)d_out;   // [2,B,D,D]
    float* out_re = out;
    float* out_im = out + PLANE;

    float* scr = nullptr;
    cudaGetSymbolAddress((void**)&scr, g_qhmm_scratch);
    float* scr_re = scr;
    float* scr_im = scr + PLANE;

    const size_t smem = (size_t)(6 * ND * DS) * sizeof(float);  // 104448 B
    cudaFuncSetAttribute(qhmm_layer_kernel,
                         cudaFuncAttributeMaxDynamicSharedMemorySize, (int)smem);

    const float* in_re = st_re;
    const float* in_im = st_im;
    for (int l = 0; l < NL; l++) {
        // Even layers -> scratch, odd layers -> d_out. NL=8 => final (l=7) lands in d_out.
        float* o_re = (l & 1) ? out_re : scr_re;
        float* o_im = (l & 1) ? out_im : scr_im;
        qhmm_layer_kernel<<<NB, 256, smem>>>(
            in_re, in_im,
            kr_re + (size_t)l * NK * MAT,
            kr_im + (size_t)l * NK * MAT,
            o_re, o_im);
        in_re = o_re;
        in_im = o_im;
    }
}

// round 15
// speedup vs baseline: 1.0036x; 1.0036x over previous
#include <cuda_runtime.h>

// Problem constants (fixed-shape problem)
#define NB 1024
#define ND 64
#define NL 8
#define NK 16
#define DS 68                 // smem row stride in floats (16B-aligned, de-conflicted)
#define MAT (ND * ND)         // 4096
#define PLANE (NB * ND * ND)  // 4,194,304

// Ping-pong scratch for intermediate rho (re plane then im plane). 32 MB static.
__device__ float g_qhmm_scratch[2 * NB * ND * ND];

typedef unsigned long long ull;

union Q4 { float4 v; ull u[2]; float f[4]; };
union P2 { ull u; float2 f; };

__device__ __forceinline__ ull dup2(float x) {
    ull r; asm("mov.b64 %0, {%1, %2};" : "=l"(r) : "f"(x), "f"(x)); return r;
}
__device__ __forceinline__ void fma2(ull& d, ull a, ull b) {
    asm("fma.rn.f32x2 %0, %1, %2, %0;" : "+l"(d) : "l"(a), "l"(b));
}
__device__ __forceinline__ ull neg2(ull a, ull negone) {
    ull r; asm("mul.rn.f32x2 %0, %1, %2;" : "=l"(r) : "l"(a), "l"(negone)); return r;
}

// One layer: for each batch b (one block), rho_out = sum_k K_k rho_in K_k^H
// Thread map: 16x16 threads, each owns a 4x4 complex tile of the 64x64 output.
//   Phase A: T = K_k @ rho     (T stored transposed in smem: Tt[l][i])
//   Phase B: C += T @ K_k^H    (accumulated in registers across k)
// K is staged transposed in smem (Kt[j][i]) so BOTH phases read it either as a
// 16B broadcast (row side) or as contiguous float4 (column side) — conflict-free.
__global__ void __launch_bounds__(256, 2)
qhmm_layer_kernel(const float* __restrict__ rin_re, const float* __restrict__ rin_im,
                  const float* __restrict__ kl_re,  const float* __restrict__ kl_im,
                  float* __restrict__ rout_re, float* __restrict__ rout_im)
{
    extern __shared__ float s[];
    float* s_rr = s;                 // rho real   [j][l], stride DS
    float* s_ri = s_rr + ND * DS;    // rho imag
    float* s_kr = s_ri + ND * DS;    // Kt real    [j][i]  (K transposed)
    float* s_ki = s_kr + ND * DS;    // Kt imag
    float* s_tr = s_ki + ND * DS;    // Tt real    [l][i]  (T transposed)
    float* s_ti = s_tr + ND * DS;    // Tt imag

    const int b   = blockIdx.x;
    const int tid = threadIdx.x;
    const int tx  = tid & 15;
    const int ty  = tid >> 4;
    const int i0  = ty * 4;   // output row base
    const int c0  = tx * 4;   // output col base (l in phase A, m in phase B)

    // Load rho for this batch into smem (coalesced reads, stride-DS rows).
    {
        const float* gr = rin_re + b * MAT;
        const float* gi = rin_im + b * MAT;
        #pragma unroll
        for (int e = tid; e < MAT; e += 256) {
            int i = e >> 6, j = e & 63;
            s_rr[i * DS + j] = gr[e];
            s_ri[i * DS + j] = gi[e];
        }
    }

    // Output accumulators: C[i0+ii][c0 + 2p + {0,1}], packed f32x2 along columns.
    ull cr[4][2], ci[4][2];
    #pragma unroll
    for (int a = 0; a < 4; a++) {
        #pragma unroll
        for (int p = 0; p < 2; p++) { cr[a][p] = 0ull; ci[a][p] = 0ull; }
    }

    const ull NEG1 = dup2(-1.0f);

    for (int k = 0; k < NK; k++) {
        __syncthreads();  // previous phase B done reading s_k*/s_t*
        // Stage K_k transposed: Kt[j][i] = K[i][j]
        {
            const float* gkr = kl_re + k * MAT;
            const float* gki = kl_im + k * MAT;
            #pragma unroll
            for (int e = tid; e < MAT; e += 256) {
                int i = e >> 6, j = e & 63;
                s_kr[j * DS + i] = gkr[e];
                s_ki[j * DS + i] = gki[e];
            }
        }
        __syncthreads();

        // ---- Phase A: T[i][l] = sum_j K[i][j] * rho[j][l] ----
        ull tr[4][2], ti[4][2];
        #pragma unroll
        for (int a = 0; a < 4; a++) {
            #pragma unroll
            for (int p = 0; p < 2; p++) { tr[a][p] = 0ull; ti[a][p] = 0ull; }
        }
        #pragma unroll 4
        for (int j = 0; j < ND; j++) {
            Q4 ar4, ai4, br4, bi4;
            ar4.v = *(const float4*)(s_kr + j * DS + i0);  // K[i0..i0+3][j] (broadcast)
            ai4.v = *(const float4*)(s_ki + j * DS + i0);
            br4.v = *(const float4*)(s_rr + j * DS + c0);  // rho[j][c0..c0+3] (vector)
            bi4.v = *(const float4*)(s_ri + j * DS + c0);
            #pragma unroll
            for (int ii = 0; ii < 4; ii++) {
                ull a_r  = dup2(ar4.f[ii]);
                ull a_i  = dup2(ai4.f[ii]);
                ull na_i = neg2(a_i, NEG1);
                // tr += ar*br - ai*bi ; ti += ar*bi + ai*br
                fma2(tr[ii][0], a_r,  br4.u[0]);
                fma2(tr[ii][0], na_i, bi4.u[0]);
                fma2(tr[ii][1], a_r,  br4.u[1]);
                fma2(tr[ii][1], na_i, bi4.u[1]);
                fma2(ti[ii][0], a_r,  bi4.u[0]);
                fma2(ti[ii][0], a_i,  br4.u[0]);
                fma2(ti[ii][1], a_r,  bi4.u[1]);
                fma2(ti[ii][1], a_i,  br4.u[1]);
            }
        }
        // Write T transposed: Tt[l][i]
        #pragma unroll
        for (int ii = 0; ii < 4; ii++) {
            #pragma unroll
            for (int p = 0; p < 2; p++) {
                P2 r, m; r.u = tr[ii][p]; m.u = ti[ii][p];
                int l = c0 + 2 * p;
                s_tr[(l    ) * DS + i0 + ii] = r.f.x;
                s_tr[(l + 1) * DS + i0 + ii] = r.f.y;
                s_ti[(l    ) * DS + i0 + ii] = m.f.x;
                s_ti[(l + 1) * DS + i0 + ii] = m.f.y;
            }
        }
        __syncthreads();

        // ---- Phase B: C[i][m] += sum_l T[i][l] * conj(K[m][l]) ----
        #pragma unroll 4
        for (int l = 0; l < ND; l++) {
            Q4 ar4, ai4, br4, bi4;
            ar4.v = *(const float4*)(s_tr + l * DS + i0);  // T[i0..i0+3][l] (broadcast)
            ai4.v = *(const float4*)(s_ti + l * DS + i0);
            br4.v = *(const float4*)(s_kr + l * DS + c0);  // K[c0..c0+3][l] (vector)
            bi4.v = *(const float4*)(s_ki + l * DS + c0);
            #pragma unroll
            for (int ii = 0; ii < 4; ii++) {
                ull t_r  = dup2(ar4.f[ii]);
                ull t_i  = dup2(ai4.f[ii]);
                ull nt_r = neg2(t_r, NEG1);
                // cr += Tr*Kr + Ti*Ki ; ci += Ti*Kr - Tr*Ki   (conj on K)
                fma2(cr[ii][0], t_r,  br4.u[0]);
                fma2(cr[ii][0], t_i,  bi4.u[0]);
                fma2(cr[ii][1], t_r,  br4.u[1]);
                fma2(cr[ii][1], t_i,  bi4.u[1]);
                fma2(ci[ii][0], t_i,  br4.u[0]);
                fma2(ci[ii][0], nt_r, bi4.u[0]);
                fma2(ci[ii][1], t_i,  br4.u[1]);
                fma2(ci[ii][1], nt_r, bi4.u[1]);
            }
        }
    }

    // Write result
    float* orr = rout_re + b * MAT;
    float* ori = rout_im + b * MAT;
    #pragma unroll
    for (int ii = 0; ii < 4; ii++) {
        #pragma unroll
        for (int p = 0; p < 2; p++) {
            P2 r, m; r.u = cr[ii][p]; m.u = ci[ii][p];
            int off = (i0 + ii) * ND + c0 + 2 * p;
            *(float2*)(orr + off) = r.f;
            *(float2*)(ori + off) = m.f;
        }
    }
}

extern "C" void kernel_launch(void* const* d_in, const int* in_sizes, int n_in,
                              void* d_out, int out_size)
{
    const float* st_re = (const float*)d_in[0];  // [B,D,D]
    const float* st_im = (const float*)d_in[1];  // [B,D,D]
    const float* kr_re = (const float*)d_in[2];  // [L,K,D,D]
    const float* kr_im = (const float*)d_in[3];  // [L,K,D,D]

    float* out    = (float*)d_out;   // [2,B,D,D]
    float* out_re = out;
    float* out_im = out + PLANE;

    float* scr = nullptr;
    cudaGetSymbolAddress((void**)&scr, g_qhmm_scratch);
    float* scr_re = scr;
    float* scr_im = scr + PLANE;

    const size_t smem = (size_t)(6 * ND * DS) * sizeof(float);  // 104448 B
    cudaFuncSetAttribute(qhmm_layer_kernel,
                         cudaFuncAttributeMaxDynamicSharedMemorySize, (int)smem);

    const float* in_re = st_re;
    const float* in_im = st_im;
    for (int l = 0; l < NL; l++) {
        // Even layers -> scratch, odd layers -> d_out. NL=8 => final (l=7) lands in d_out.
        float* o_re = (l & 1) ? out_re : scr_re;
        float* o_im = (l & 1) ? out_im : scr_im;
        qhmm_layer_kernel<<<NB, 256, smem>>>(
            in_re, in_im,
            kr_re + (size_t)l * NK * MAT,
            kr_im + (size_t)l * NK * MAT,
            o_re, o_im);
        in_re = o_re;
        in_im = o_im;
    }
}